// round 11
// baseline (speedup 1.0000x reference)
#include <cuda_runtime.h>

// VanillaRNN fused persistent kernel, v9.
// B=1024, T=512, I=64, H=128, O=10.
// Grid: 128 CTAs x 8 rows = TWO independent 4-row recurrence groups per CTA.
// Block: 256 threads, ONE CTA per SM (__launch_bounds__(256,1): full register
// budget, the two groups share the same 96 weight registers).
//
// Rationale: with all warps barrier-locked each step, the serial tail
// (LDS wait + FFMA chains + 3-stage shuffle tree + tanh + STS + BAR) was
// ~1400 cyc/step exposed. Two independent groups inside one CTA give the
// in-order issue stream guaranteed independent FMA work during every
// latency window, paying the tail once per step instead of fully exposed.
//
// Thread mapping per group (v8, select-free): g = warp*4 + (lane&3): column
// group, cols {g+32*cg[c]}; seg = lane>>2 in [0,8): 24-wide k-segment of the
// 192-wide concat(x_t, h_t). Butterfly xor4/xor8/xor16 as pure
// keep + shfl_xor(send) via per-thread row/col permutation.
// tanh via MUFU tanh.approx.f32. One __syncthreads per timestep.
// Segment stride 28 floats: 8 bases tile all 32 banks -> conflict-free LDS.128.

#define ROWS 4          // rows per group
#define NGROUPS 2
#define NTHREADS 256
#define HDIM 128
#define IDIM 64
#define TSTEPS 512
#define ODIM 10
#define SEGF 24
#define SEGP 28
#define RSTRIDE 228
#define GRID 128

__device__ __forceinline__ unsigned long long ffma2(unsigned long long a,
                                                    unsigned long long b,
                                                    unsigned long long c) {
    unsigned long long d;
    asm("fma.rn.f32x2 %0, %1, %2, %3;" : "=l"(d) : "l"(a), "l"(b), "l"(c));
    return d;
}

__device__ __forceinline__ unsigned long long packf2(float lo, float hi) {
    return ((unsigned long long)__float_as_uint(hi) << 32) |
           (unsigned long long)__float_as_uint(lo);
}

__device__ __forceinline__ float sum2(unsigned long long a) {
    return __uint_as_float((unsigned)a) + __uint_as_float((unsigned)(a >> 32));
}

__device__ __forceinline__ float tanh_fast(float z) {
    float r;
    asm("tanh.approx.f32 %0, %1;" : "=f"(r) : "f"(z));
    return r;
}

__device__ __forceinline__ int physk(int k) { return k + 4 * (k / SEGF); }

__device__ __forceinline__ float wpick(const float* __restrict__ W_hx,
                                       const float* __restrict__ W_hh,
                                       int o, int k) {
    return (k < IDIM) ? W_hx[o * IDIM + k] : W_hh[o * HDIM + (k - IDIM)];
}

// accumulate one row's 24-k segment for this thread's 4 (permuted) cols
__device__ __forceinline__ void row_acc(const float* __restrict__ rowseg,
                                        const unsigned long long w[4][12],
                                        float sv[4]) {
    const ulonglong2* pp = (const ulonglong2*)rowseg;
    unsigned long long a0 = 0ull, a1 = 0ull, a2 = 0ull, a3 = 0ull;
#pragma unroll
    for (int i = 0; i < 6; i++) {
        ulonglong2 v = pp[i];
        a0 = ffma2(v.x, w[0][2 * i], a0);
        a1 = ffma2(v.x, w[1][2 * i], a1);
        a2 = ffma2(v.x, w[2][2 * i], a2);
        a3 = ffma2(v.x, w[3][2 * i], a3);
        a0 = ffma2(v.y, w[0][2 * i + 1], a0);
        a1 = ffma2(v.y, w[1][2 * i + 1], a1);
        a2 = ffma2(v.y, w[2][2 * i + 1], a2);
        a3 = ffma2(v.y, w[3][2 * i + 1], a3);
    }
    sv[0] = sum2(a0); sv[1] = sum2(a1); sv[2] = sum2(a2); sv[3] = sum2(a3);
}

__global__ void __launch_bounds__(NTHREADS, 1)
rnn_fused_kernel(const float* __restrict__ x,
                 const float* __restrict__ W_hx,
                 const float* __restrict__ W_hh,
                 const float* __restrict__ b_hh,
                 const float* __restrict__ W_ph,
                 const float* __restrict__ b_ph,
                 float* __restrict__ out) {
    // buf[group][pingpong][row][phys-k]
    __shared__ __align__(16) float buf[NGROUPS][2][ROWS][RSTRIDE];

    const int tid  = threadIdx.x;
    const int lane = tid & 31;
    const int warp = tid >> 5;
    const int g    = warp * 4 + (lane & 3);   // col group 0..31
    const int seg  = lane >> 2;               // k-segment 0..7
    const int kb   = seg * SEGF;
    const int b0r  = blockIdx.x * (ROWS * NGROUPS);

    const int sb0 = seg & 1, sb1 = (seg >> 1) & 1, sb2 = (seg >> 2) & 1;

    // per-thread permuted column order (stage-2 select elimination)
    int cg[4];
    cg[0] = 2 * sb2; cg[1] = 2 * sb2 + 1;
    cg[2] = 2 * (1 - sb2); cg[3] = 2 * (1 - sb2) + 1;

    // ---- weights in permuted col order: 48 ULL = 96 regs, SHARED by groups
    unsigned long long w[4][12];
#pragma unroll
    for (int c = 0; c < 4; c++) {
        const int o = g + 32 * cg[c];
#pragma unroll
        for (int j = 0; j < 12; j++) {
            const int k0 = kb + 2 * j;
            w[c][j] = packf2(wpick(W_hx, W_hh, o, k0),
                             wpick(W_hx, W_hh, o, k0 + 1));
        }
    }

    // per-thread row order (stage-0/1 select elimination)
    const int rKA = sb1 + 2 * sb0;
    const int rSA = sb1 + 2 * (1 - sb0);
    const int rKB = (1 - sb1) + 2 * sb0;
    const int rSB = (1 - sb1) + 2 * (1 - sb0);
    const int segoff = seg * SEGP;
    const int oKA = rKA * RSTRIDE + segoff;
    const int oSA = rSA * RSTRIDE + segoff;
    const int oKB = rKB * RSTRIDE + segoff;
    const int oSB = rSB * RSTRIDE + segoff;

    const int mstar = 2 * sb0 + sb1;          // row this lane finalizes
    const int of0 = g + 32 * cg[0];
    const int of1 = g + 32 * cg[1];
    const float bb0 = b_hh[of0];
    const float bb1 = b_hh[of1];
    const int ph0 = physk(IDIM + of0);
    const int ph1 = physk(IDIM + of1);

    // ---- zero all buffers (h0 = 0)
    for (int i = tid; i < NGROUPS * 2 * ROWS * RSTRIDE; i += NTHREADS)
        ((float*)buf)[i] = 0.0f;

    // ---- x loader: tid<128 -> global row xr = tid>>4 (0..7), chunk c4
    const int xr   = tid >> 4;                // 0..15; valid rows when tid<128
    const int xgrp = (xr >> 2) & 1;           // group of this loader row
    const int xrl  = xr & 3;                  // row within group
    const int c4   = (tid & 15) * 4;
    const int pc4  = c4 + 4 * (c4 / SEGF);
    const bool loader = (tid < 128);
    const float* xrow = x + (size_t)(b0r + (xr & 7)) * TSTEPS * IDIM;

    if (loader)
        *(float4*)&buf[xgrp][0][xrl][pc4] = *(const float4*)(xrow + c4);
    __syncthreads();

    int p = 0;
    for (int t = 0; t < TSTEPS; t++) {
        float4 xn;
        if (loader) {
            const int tn = (t + 1 < TSTEPS) ? t + 1 : TSTEPS - 1;
            xn = *(const float4*)(xrow + (size_t)tn * IDIM + c4);
        }

        const float* base0 = &buf[0][p][0][0];
        const float* base1 = &buf[1][p][0][0];

        // ---- accumulate BOTH groups first: 8 row_accs, 32 live floats.
        // Independent chains -> the issue stream always has FMA work while
        // any shuffle/LDS below is in flight.
        float aKA0[4], aSA0[4], aKB0[4], aSB0[4];
        float aKA1[4], aSA1[4], aKB1[4], aSB1[4];
        row_acc(base0 + oKA, w, aKA0);
        row_acc(base0 + oSA, w, aSA0);
        row_acc(base1 + oKA, w, aKA1);
        row_acc(base1 + oSA, w, aSA1);
        row_acc(base0 + oKB, w, aKB0);
        row_acc(base0 + oSB, w, aSB0);
        row_acc(base1 + oKB, w, aKB1);
        row_acc(base1 + oSB, w, aSB1);

        // ---- stage 0 (xor 4), both groups interleaved
        float ra0[4], rb0[4], ra1[4], rb1[4];
#pragma unroll
        for (int c = 0; c < 4; c++) {
            ra0[c] = aKA0[c] + __shfl_xor_sync(0xffffffffu, aSA0[c], 4);
            ra1[c] = aKA1[c] + __shfl_xor_sync(0xffffffffu, aSA1[c], 4);
            rb0[c] = aKB0[c] + __shfl_xor_sync(0xffffffffu, aSB0[c], 4);
            rb1[c] = aKB1[c] + __shfl_xor_sync(0xffffffffu, aSB1[c], 4);
        }

        // ---- stage 1 (xor 8)
        float rc0[4], rc1[4];
#pragma unroll
        for (int c = 0; c < 4; c++) {
            rc0[c] = ra0[c] + __shfl_xor_sync(0xffffffffu, rb0[c], 8);
            rc1[c] = ra1[c] + __shfl_xor_sync(0xffffffffu, rb1[c], 8);
        }

        // ---- stage 2 (xor 16)
        const float f00 = rc0[0] + __shfl_xor_sync(0xffffffffu, rc0[2], 16);
        const float f10 = rc1[0] + __shfl_xor_sync(0xffffffffu, rc1[2], 16);
        const float f01 = rc0[1] + __shfl_xor_sync(0xffffffffu, rc0[3], 16);
        const float f11 = rc1[1] + __shfl_xor_sync(0xffffffffu, rc1[3], 16);

        // ---- publish h_t for both groups
        const int q = p ^ 1;
        buf[0][q][mstar][ph0] = tanh_fast(f00 + bb0);
        buf[0][q][mstar][ph1] = tanh_fast(f01 + bb1);
        buf[1][q][mstar][ph0] = tanh_fast(f10 + bb0);
        buf[1][q][mstar][ph1] = tanh_fast(f11 + bb1);

        if (loader) *(float4*)&buf[xgrp][q][xrl][pc4] = xn;

        __syncthreads();
        p = q;
    }

    // ---- final projection over all 8 rows
    if (tid < ROWS * NGROUPS * ODIM) {
        const int m = tid / ODIM;             // 0..7
        const int j = tid % ODIM;
        const int mg = m >> 2, mr = m & 3;
        float s = b_ph[j];
#pragma unroll 4
        for (int k = 0; k < HDIM; k++)
            s += buf[mg][p][mr][physk(IDIM + k)] * W_ph[j * HDIM + k];
        out[(size_t)(b0r + m) * ODIM + j] = s;
    }
}

extern "C" void kernel_launch(void* const* d_in, const int* in_sizes, int n_in,
                              void* d_out, int out_size) {
    const float* x    = (const float*)d_in[0];
    const float* W_hx = (const float*)d_in[1];
    const float* W_hh = (const float*)d_in[2];
    const float* b_hh = (const float*)d_in[3];
    const float* W_ph = (const float*)d_in[4];
    const float* b_ph = (const float*)d_in[5];
    float* out = (float*)d_out;

    rnn_fused_kernel<<<GRID, NTHREADS>>>(x, W_hx, W_hh, b_hh, W_ph, b_ph, out);
}